// round 1
// baseline (speedup 1.0000x reference)
#include <cuda_runtime.h>
#include <math.h>

#define B_N        262144
#define CHUNK      2048
#define HALO       64
#define HC         (CHUNK + HALO)
#define NBLK       (B_N / CHUNK)          // 128
#define TPB        256
#define SEG        (CHUNK / TPB)          // 8
#define RED_BLOCKS 256
#define SPIN_LEN   365
#define TRAIN_LEN  200000
#define N_OBS      (TRAIN_LEN - SPIN_LEN) // 199635
#define ML_C       2.9086f
#define SL_C       1.898f

struct Scalars {
    float oo, oogw, ol1, fbase, b0, wb2, obsstd;
};
__device__ Scalars g_sc;
__device__ float   g_part[RED_BLOCKS][2];

// ---------------------------------------------------------------------------
// K1: per-block partial (sum, sumsq) over y_obs[SPIN_LEN:TRAIN_LEN]
// ---------------------------------------------------------------------------
__global__ void k_reduce(const float* __restrict__ y) {
    float s = 0.f, s2 = 0.f;
    for (int i = blockIdx.x * blockDim.x + threadIdx.x; i < N_OBS;
         i += gridDim.x * blockDim.x) {
        float v = y[SPIN_LEN + i];
        s  += v;
        s2 += v * v;
    }
#pragma unroll
    for (int o = 16; o; o >>= 1) {
        s  += __shfl_down_sync(0xffffffffu, s, o);
        s2 += __shfl_down_sync(0xffffffffu, s2, o);
    }
    __shared__ float shs[8], shs2[8];
    int w = threadIdx.x >> 5, l = threadIdx.x & 31;
    if (l == 0) { shs[w] = s; shs2[w] = s2; }
    __syncthreads();
    if (threadIdx.x == 0) {
        float a = 0.f, b = 0.f;
#pragma unroll
        for (int i = 0; i < TPB / 32; i++) { a += shs[i]; b += shs2[i]; }
        g_part[blockIdx.x][0] = a;
        g_part[blockIdx.x][1] = b;
    }
}

// ---------------------------------------------------------------------------
// K2: finalize obsstd (double precision) + softmax scalar gates
// ---------------------------------------------------------------------------
__global__ void k_final(const float* __restrict__ w_yom,
                        const float* __restrict__ w_gw,
                        const float* __restrict__ w_lm,
                        const float* __restrict__ w_fm,
                        const float* __restrict__ b0p,
                        const float* __restrict__ wb2p) {
    int t = threadIdx.x;  // 256 threads, one per partial
    double s  = (double)g_part[t][0];
    double s2 = (double)g_part[t][1];
#pragma unroll
    for (int o = 16; o; o >>= 1) {
        s  += __shfl_down_sync(0xffffffffu, s, o);
        s2 += __shfl_down_sync(0xffffffffu, s2, o);
    }
    __shared__ double shs[8], shs2[8];
    int w = t >> 5, l = t & 31;
    if (l == 0) { shs[w] = s; shs2[w] = s2; }
    __syncthreads();
    if (t == 0) {
        double S = 0.0, S2 = 0.0;
#pragma unroll
        for (int i = 0; i < 8; i++) { S += shs[i]; S2 += shs2[i]; }
        double n   = (double)N_OBS;
        double var = (S2 - S * S / n) / (n - 1.0);

        float e1 = expf(w_yom[0]);
        float e2 = expf(w_gw[0]);
        float e3 = expf(w_lm[0]);
        float e4 = expf(w_fm[0]);
        float denom = e1 + e2 + e3 + e4;

        Scalars sc;
        sc.oo     = e1 / denom;
        sc.oogw   = e2 / denom;
        sc.ol1    = e3 / denom;
        sc.fbase  = 1.0f - sc.oo - sc.oogw;   // f = fbase - ol
        sc.b0     = b0p[0];
        sc.wb2    = wb2p[0];
        sc.obsstd = (float)sqrt(var);
        g_sc = sc;
    }
}

// ---------------------------------------------------------------------------
// K3: halo-parallel linear recurrence + all 13 output arrays (coalesced)
// ---------------------------------------------------------------------------
__global__ void __launch_bounds__(TPB)
k_main(const float2* __restrict__ x, float* __restrict__ out) {
    __shared__ float u1s[HC], fs[HC], ols[HC], c0s[CHUNK];

    const Scalars sc = g_sc;
    const int bstart = blockIdx.x * CHUNK;
    const float inv_sl = 1.0f / SL_C;

    // Phase 1: load x, compute ol/f once per element (incl. 64-elem halo)
    for (int s = threadIdx.x; s < HC; s += TPB) {
        int g = bstart - HALO + s;
        float u1 = 0.f, fv = 0.f, olv = 0.f;
        if (g >= 0) {
            float2 v = x[g];
            u1 = v.x;
            float z   = sc.b0 + (v.y - ML_C) * inv_sl * sc.wb2;
            float sig = 1.0f / (1.0f + expf(-z));
            olv = sc.ol1 * sig;
            fv  = sc.fbase - olv;
        }
        u1s[s] = u1; fs[s] = fv; ols[s] = olv;
    }
    __syncthreads();

    // Phase 2: per-thread scan with halo (f <= 0.731 => halo error ~2e-9)
    {
        const int base = HALO + threadIdx.x * SEG;
        float c = 0.f;
#pragma unroll
        for (int p = 0; p < HALO; ++p) {
            int q = base - HALO + p;
            c = fmaf(fs[q], c, u1s[q]);
        }
#pragma unroll
        for (int p = 0; p < SEG; ++p) {
            int q = base + p;
            c0s[q - HALO] = c;            // pre-update state c0[t]
            c = fmaf(fs[q], c, u1s[q]);
        }
    }
    __syncthreads();

    // Phase 3: coalesced writes of all 12 (13 incl. h_nout's 2 cols) outputs
    float* __restrict__ h_n   = out;
    float* __restrict__ c_n   = out +  1 * B_N;
    float* __restrict__ l_n   = out +  2 * B_N;
    float* __restrict__ gw_n  = out +  3 * B_N;
    float* __restrict__ bp_n  = out +  4 * B_N;
    float* __restrict__ gib   = out +  5 * B_N;
    float* __restrict__ goo   = out +  6 * B_N;
    float* __restrict__ googw = out +  7 * B_N;
    float* __restrict__ gol   = out +  8 * B_N;
    float* __restrict__ gf    = out +  9 * B_N;
    float* __restrict__ hnout = out + 10 * B_N;   // (B,2) row-major
    float* __restrict__ obss  = out + 12 * B_N;

    for (int i = threadIdx.x; i < CHUNK; i += TPB) {
        int g = bstart + i;
        float c0  = c0s[i];
        float olv = ols[i + HALO];
        float fv  = fs[i + HALO];
        float h   = sc.oo * c0;
        h_n[g]         = h;
        c_n[g]         = c0;
        l_n[g]         = olv * c0;
        gw_n[g]        = sc.oogw * c0;
        bp_n[g]        = 0.f;
        gib[g]         = 0.f;
        goo[g]         = sc.oo;
        googw[g]       = sc.oogw;
        gol[g]         = olv;
        gf[g]          = fv;
        hnout[2*g]     = h;
        hnout[2*g + 1] = sc.obsstd;
        obss[g]        = sc.obsstd;
    }
}

// ---------------------------------------------------------------------------
extern "C" void kernel_launch(void* const* d_in, const int* in_sizes, int n_in,
                              void* d_out, int out_size) {
    const float* x = (const float*)d_in[0];
    const float* y = (const float*)d_in[1];

    // Inputs per setup_inputs order: x, y_obs, epoch, time_lag, then the 6
    // float scalars. If the integer scalars aren't materialized as buffers,
    // the float params shift by 2.
    int base = (n_in >= 10) ? 4 : 2;
    const float* w_yom = (const float*)d_in[base + 0];
    const float* w_gw  = (const float*)d_in[base + 1];
    const float* w_lm  = (const float*)d_in[base + 2];
    const float* w_fm  = (const float*)d_in[base + 3];
    const float* b0p   = (const float*)d_in[base + 4];
    const float* wb2p  = (const float*)d_in[base + 5];

    k_reduce<<<RED_BLOCKS, TPB>>>(y);
    k_final<<<1, TPB>>>(w_yom, w_gw, w_lm, w_fm, b0p, wb2p);
    k_main<<<NBLK, TPB>>>((const float2*)x, (float*)d_out);
}